// round 6
// baseline (speedup 1.0000x reference)
#include <cuda_runtime.h>
#include <cstdint>

#define N_NODES 50000
#define N_EDGES 800000
#define DIM 128
#define SCAN_NB ((N_NODES + 255) / 256)   // 196 blocks

// Scratch (device globals)
__device__ int   g_cnt[N_NODES];
__device__ int   g_off[N_NODES + 1];
__device__ int   g_cur[N_NODES];
__device__ int   g_bsum[SCAN_NB];
__device__ int   g_boff[SCAN_NB];
__device__ float g_dinv[N_NODES];
__device__ int2  g_edge[N_EDGES];        // {src, norm bits} CSR-by-dst order
__device__ float g_tmp[N_NODES * DIM];
__device__ float g_h[N_NODES * DIM];

// ---------------- degree / CSR build ----------------
__global__ void k_zero_cnt() {
    int i = blockIdx.x * blockDim.x + threadIdx.x;
    if (i < N_NODES) g_cnt[i] = 0;
}

__global__ void k_hist(const int* __restrict__ ei) {
    int e = blockIdx.x * blockDim.x + threadIdx.x;
    if (e < N_EDGES) atomicAdd(&g_cnt[ei[N_EDGES + e]], 1);
}

// scan phase 1 + dinv fused
__global__ void k_scan1() {
    __shared__ int s[256];
    int tid = threadIdx.x;
    int i = blockIdx.x * 256 + tid;
    int v = (i < N_NODES) ? g_cnt[i] : 0;
    if (i < N_NODES) g_dinv[i] = rsqrtf((float)(v + 1));   // +1 self-loop
    s[tid] = v;
    __syncthreads();
#pragma unroll
    for (int d = 1; d < 256; d <<= 1) {
        int t = (tid >= d) ? s[tid - d] : 0;
        __syncthreads();
        s[tid] += t;
        __syncthreads();
    }
    if (i < N_NODES) g_off[i] = s[tid] - v;
    if (tid == 255) g_bsum[blockIdx.x] = s[255];
}

__global__ void k_scan2() {
    __shared__ int s[SCAN_NB];
    int tid = threadIdx.x;
    int v = (tid < SCAN_NB) ? g_bsum[tid] : 0;
    if (tid < SCAN_NB) s[tid] = v;
    __syncthreads();
    for (int d = 1; d < SCAN_NB; d <<= 1) {
        int t = (tid >= d && tid < SCAN_NB) ? s[tid - d] : 0;
        __syncthreads();
        if (tid < SCAN_NB) s[tid] += t;
        __syncthreads();
    }
    if (tid < SCAN_NB) g_boff[tid] = s[tid] - v;
}

__global__ void k_scan3() {
    int i = blockIdx.x * blockDim.x + threadIdx.x;
    if (i < N_NODES) {
        int o = g_off[i] + g_boff[i >> 8];
        g_off[i] = o;
        g_cur[i] = o;
    }
    if (i == 0) g_off[N_NODES] = N_EDGES;
}

__global__ void k_scatter(const int* __restrict__ ei) {
    int e = blockIdx.x * blockDim.x + threadIdx.x;
    if (e >= N_EDGES) return;
    int src = ei[e];
    int dst = ei[N_EDGES + e];
    int pos = atomicAdd(&g_cur[dst], 1);
    float norm = g_dinv[src] * g_dinv[dst];
    g_edge[pos] = make_int2(src, __float_as_int(norm));
}

// ---------------- tf32 tensor-core GEMM (rna-rounded at fill) ----------------
__device__ __forceinline__ uint32_t to_tf32(float a) {
    uint32_t h;
    asm("cvt.rna.tf32.f32 %0, %1;" : "=r"(h) : "f"(a));
    return h;
}

__device__ __forceinline__ void mma_tf32(float* d, const uint32_t* a, const uint32_t* b) {
    asm volatile(
        "mma.sync.aligned.m16n8k8.row.col.f32.tf32.tf32.f32 "
        "{%0,%1,%2,%3},{%4,%5,%6,%7},{%8,%9},{%0,%1,%2,%3};"
        : "+f"(d[0]), "+f"(d[1]), "+f"(d[2]), "+f"(d[3])
        : "r"(a[0]), "r"(a[1]), "r"(a[2]), "r"(a[3]), "r"(b[0]), "r"(b[1]));
}

#define XSTRIDE 20     // words; (20*g + tg) mod 32 all-distinct across warp
#define WSTRIDE 24     // words per n-row (16 used); conflict-free LDS.64 per half-warp

template<bool RELU>
__global__ void __launch_bounds__(256, 2)
k_gemm(const float* __restrict__ X, const float* __restrict__ W,
       float* __restrict__ Out) {
    __shared__ uint32_t sX[128 * XSTRIDE];   // [row][k] tf32, 10 KB
    __shared__ uint32_t sWT[128 * WSTRIDE];  // [n][k interleaved] tf32, 12 KB

    int tid  = threadIdx.x;
    int warp = tid >> 5;
    int lane = tid & 31;
    int g    = lane >> 2;      // groupID
    int tg   = lane & 3;       // thread-in-group
    int row0 = blockIdx.x * 128;
    int rb   = warp * 16;      // warp row base

    float acc[16][4];
#pragma unroll
    for (int n = 0; n < 16; n++)
#pragma unroll
        for (int c = 0; c < 4; c++) acc[n][c] = 0.f;

    for (int kk = 0; kk < DIM; kk += 16) {
        // X chunk: 128 rows x 16 k, tf32-rounded  (2 float4 per thread)
#pragma unroll
        for (int i = 0; i < 2; i++) {
            int idx = i * 256 + tid;
            int r = idx >> 2, c4 = (idx & 3) * 4;
            int row = row0 + r;
            float4 v = make_float4(0.f, 0.f, 0.f, 0.f);
            if (row < N_NODES) v = *(const float4*)&X[row * DIM + kk + c4];
            if (RELU) {
                v.x = fmaxf(v.x, 0.f); v.y = fmaxf(v.y, 0.f);
                v.z = fmaxf(v.z, 0.f); v.w = fmaxf(v.w, 0.f);
            }
            uint32_t* p = &sX[r * XSTRIDE + c4];
            p[0] = to_tf32(v.x); p[1] = to_tf32(v.y);
            p[2] = to_tf32(v.z); p[3] = to_tf32(v.w);
        }
        // W chunk transposed + k-interleaved: value W[kk+k][n] -> sWT[n][8*(k>>3) + 2*(k&3) + ((k>>2)&1)]
#pragma unroll
        for (int i = 0; i < 2; i++) {
            int idx = i * 256 + tid;
            int k = idx >> 5, c4 = (idx & 31) * 4;
            float4 v = *(const float4*)&W[(kk + k) * DIM + c4];
            int slot = 8 * (k >> 3) + 2 * (k & 3) + ((k >> 2) & 1);
            sWT[(c4 + 0) * WSTRIDE + slot] = to_tf32(v.x);
            sWT[(c4 + 1) * WSTRIDE + slot] = to_tf32(v.y);
            sWT[(c4 + 2) * WSTRIDE + slot] = to_tf32(v.z);
            sWT[(c4 + 3) * WSTRIDE + slot] = to_tf32(v.w);
        }
        __syncthreads();

#pragma unroll
        for (int k8 = 0; k8 < 16; k8 += 8) {
            uint32_t a[4];
            a[0] = sX[(rb + g    ) * XSTRIDE + k8 + tg    ];
            a[1] = sX[(rb + g + 8) * XSTRIDE + k8 + tg    ];
            a[2] = sX[(rb + g    ) * XSTRIDE + k8 + tg + 4];
            a[3] = sX[(rb + g + 8) * XSTRIDE + k8 + tg + 4];
            int koff = (k8 >> 3) * 8 + 2 * tg;
#pragma unroll
            for (int nt = 0; nt < 16; nt++) {
                uint32_t b[2];
                *(uint2*)b = *(uint2*)&sWT[(nt * 8 + g) * WSTRIDE + koff];
                mma_tf32(acc[nt], a, b);
            }
        }
        __syncthreads();
    }

    int r_lo = row0 + rb + g;
    int r_hi = r_lo + 8;
#pragma unroll
    for (int nt = 0; nt < 16; nt++) {
        int col = nt * 8 + 2 * tg;
        if (r_lo < N_NODES)
            *(float2*)&Out[r_lo * DIM + col] = make_float2(acc[nt][0], acc[nt][1]);
        if (r_hi < N_NODES)
            *(float2*)&Out[r_hi * DIM + col] = make_float2(acc[nt][2], acc[nt][3]);
    }
}

// ---------------- CSR gather aggregation ----------------
__global__ void k_gather(const float* __restrict__ tmp, const float* __restrict__ bias,
                         float* __restrict__ out) {
    int node = (int)((blockIdx.x * (unsigned)blockDim.x + threadIdx.x) >> 5);
    int lane = threadIdx.x & 31;
    if (node >= N_NODES) return;

    int beg = g_off[node];
    int end = g_off[node + 1];
    float dd = g_dinv[node];
    float self = dd * dd;

    float4 v = *(const float4*)&tmp[node * DIM + lane * 4];
    float4 acc = make_float4(v.x * self, v.y * self, v.z * self, v.w * self);

    int e = beg;
    for (; e + 3 < end; e += 4) {
        int2 m0 = g_edge[e + 0];
        int2 m1 = g_edge[e + 1];
        int2 m2 = g_edge[e + 2];
        int2 m3 = g_edge[e + 3];
        float4 v0 = *(const float4*)&tmp[m0.x * DIM + lane * 4];
        float4 v1 = *(const float4*)&tmp[m1.x * DIM + lane * 4];
        float4 v2 = *(const float4*)&tmp[m2.x * DIM + lane * 4];
        float4 v3 = *(const float4*)&tmp[m3.x * DIM + lane * 4];
        float n0 = __int_as_float(m0.y), n1 = __int_as_float(m1.y);
        float n2 = __int_as_float(m2.y), n3 = __int_as_float(m3.y);
        acc.x += v0.x * n0 + v1.x * n1 + v2.x * n2 + v3.x * n3;
        acc.y += v0.y * n0 + v1.y * n1 + v2.y * n2 + v3.y * n3;
        acc.z += v0.z * n0 + v1.z * n1 + v2.z * n2 + v3.z * n3;
        acc.w += v0.w * n0 + v1.w * n1 + v2.w * n2 + v3.w * n3;
    }
    for (; e < end; e++) {
        int2 m0 = g_edge[e];
        float n0 = __int_as_float(m0.y);
        float4 v0 = *(const float4*)&tmp[m0.x * DIM + lane * 4];
        acc.x += v0.x * n0; acc.y += v0.y * n0;
        acc.z += v0.z * n0; acc.w += v0.w * n0;
    }

    float4 bb = *(const float4*)&bias[lane * 4];
    acc.x += bb.x; acc.y += bb.y; acc.z += bb.z; acc.w += bb.w;
    *(float4*)&out[node * DIM + lane * 4] = acc;
}

// ---------------- launch ----------------
extern "C" void kernel_launch(void* const* d_in, const int* in_sizes, int n_in,
                              void* d_out, int out_size) {
    const float* x  = (const float*)d_in[0];
    const int*   ei = (const int*)d_in[1];
    const float* W1 = (const float*)d_in[2];
    const float* b1 = (const float*)d_in[3];
    const float* W2 = (const float*)d_in[4];
    const float* b2 = (const float*)d_in[5];
    float* out = (float*)d_out;

    float* tmp_p; cudaGetSymbolAddress((void**)&tmp_p, g_tmp);
    float* h_p;   cudaGetSymbolAddress((void**)&h_p,   g_h);

    int nthr = 256;
    int nb_nodes  = (N_NODES + nthr - 1) / nthr;
    int nb_edges  = (N_EDGES + nthr - 1) / nthr;
    int nb_gemm   = (N_NODES + 127) / 128;
    int nb_gather = (N_NODES * 32 + nthr - 1) / nthr;

    // CSR build (by destination) + normalization
    k_zero_cnt<<<nb_nodes, nthr>>>();
    k_hist<<<nb_edges, nthr>>>(ei);
    k_scan1<<<SCAN_NB, 256>>>();
    k_scan2<<<1, 256>>>();
    k_scan3<<<SCAN_NB, 256>>>();
    k_scatter<<<nb_edges, nthr>>>(ei);

    // layer 1
    k_gemm<false><<<nb_gemm, nthr>>>(x, W1, tmp_p);
    k_gather<<<nb_gather, nthr>>>(tmp_p, b1, h_p);

    // layer 2
    k_gemm<true><<<nb_gemm, nthr>>>(h_p, W2, tmp_p);
    k_gather<<<nb_gather, nthr>>>(tmp_p, b2, out);
}

// round 7
// speedup vs baseline: 1.1552x; 1.1552x over previous
#include <cuda_runtime.h>
#include <cstdint>

#define N_NODES 50000
#define N_EDGES 800000
#define DIM 128
#define SCAN_NB ((N_NODES + 255) / 256)   // 196 blocks

// Scratch (device globals)
__device__ int   g_cnt[N_NODES];
__device__ int   g_off[N_NODES + 1];
__device__ int   g_cur[N_NODES];
__device__ int   g_bsum[SCAN_NB];
__device__ float g_dinv[N_NODES];
__device__ int2  g_edge[N_EDGES];        // {src, norm bits} CSR-by-dst order
__device__ float g_tmp[N_NODES * DIM];
__device__ float g_h[N_NODES * DIM];

// ---------------- degree / CSR build ----------------
__global__ void k_zero_cnt() {
    int i = blockIdx.x * blockDim.x + threadIdx.x;
    if (i < N_NODES) g_cnt[i] = 0;
}

__global__ void k_hist(const int* __restrict__ ei) {
    int e = blockIdx.x * blockDim.x + threadIdx.x;
    if (e < N_EDGES) atomicAdd(&g_cnt[ei[N_EDGES + e]], 1);
}

// scan phase 1 + dinv fused: local exclusive prefix + per-block sums
__global__ void k_scan1() {
    __shared__ int s[256];
    int tid = threadIdx.x;
    int i = blockIdx.x * 256 + tid;
    int v = (i < N_NODES) ? g_cnt[i] : 0;
    if (i < N_NODES) g_dinv[i] = rsqrtf((float)(v + 1));   // +1 self-loop
    s[tid] = v;
    __syncthreads();
#pragma unroll
    for (int d = 1; d < 256; d <<= 1) {
        int t = (tid >= d) ? s[tid - d] : 0;
        __syncthreads();
        s[tid] += t;
        __syncthreads();
    }
    if (i < N_NODES) g_off[i] = s[tid] - v;
    if (tid == 255) g_bsum[blockIdx.x] = s[255];
}

// scan phase 2: each block redundantly reduces its own global offset, then adds.
__global__ void k_scan3() {
    __shared__ int red[256];
    int b = blockIdx.x;
    int t = threadIdx.x;
    int partial = 0;
    for (int j = t; j < b; j += 256) partial += g_bsum[j];
    red[t] = partial;
    __syncthreads();
#pragma unroll
    for (int d = 128; d > 0; d >>= 1) {
        if (t < d) red[t] += red[t + d];
        __syncthreads();
    }
    int boff = red[0];
    int i = b * 256 + t;
    if (i < N_NODES) {
        int o = g_off[i] + boff;
        g_off[i] = o;
        g_cur[i] = o;
    }
    if (i == 0) g_off[N_NODES] = N_EDGES;
}

__global__ void k_scatter(const int* __restrict__ ei) {
    int e = blockIdx.x * blockDim.x + threadIdx.x;
    if (e >= N_EDGES) return;
    int src = ei[e];
    int dst = ei[N_EDGES + e];
    int pos = atomicAdd(&g_cur[dst], 1);
    float norm = g_dinv[src] * g_dinv[dst];
    g_edge[pos] = make_int2(src, __float_as_int(norm));
}

// ---------------- FFMA GEMM: Out[N,128] = act(X)[N,128] @ W[128,128] ----------------
template<bool RELU>
__global__ void __launch_bounds__(256, 2)
k_gemm(const float* __restrict__ X, const float* __restrict__ W,
       float* __restrict__ Out) {
    __shared__ float sW[16][DIM];
    __shared__ float sX[16][132];

    int tid = threadIdx.x;
    int tc = tid & 15, tr = tid >> 4;
    int row0 = blockIdx.x * 128;

    float acc[8][8];
#pragma unroll
    for (int r = 0; r < 8; r++)
#pragma unroll
        for (int c = 0; c < 8; c++) acc[r][c] = 0.f;

    for (int kk = 0; kk < DIM; kk += 16) {
#pragma unroll
        for (int i = 0; i < 2; i++) {
            int lin = (i * 256 + tid) * 4;
            int k = lin >> 7, c = lin & 127;
            *(float4*)&sW[k][c] = *(const float4*)&W[(kk + k) * DIM + c];
        }
#pragma unroll
        for (int i = 0; i < 2; i++) {
            int lin = (i * 256 + tid) * 4;
            int r = lin >> 4, c = lin & 15;
            int row = row0 + r;
            float4 v = make_float4(0.f, 0.f, 0.f, 0.f);
            if (row < N_NODES) v = *(const float4*)&X[row * DIM + kk + c];
            if (RELU) {
                v.x = fmaxf(v.x, 0.f); v.y = fmaxf(v.y, 0.f);
                v.z = fmaxf(v.z, 0.f); v.w = fmaxf(v.w, 0.f);
            }
            sX[c + 0][r] = v.x; sX[c + 1][r] = v.y;
            sX[c + 2][r] = v.z; sX[c + 3][r] = v.w;
        }
        __syncthreads();

#pragma unroll
        for (int k = 0; k < 16; k++) {
            float a[8], b[8];
            *(float4*)&b[0] = *(float4*)&sW[k][tc * 4];
            *(float4*)&b[4] = *(float4*)&sW[k][tc * 4 + 64];
            *(float4*)&a[0] = *(float4*)&sX[k][tr * 8];
            *(float4*)&a[4] = *(float4*)&sX[k][tr * 8 + 4];
#pragma unroll
            for (int r = 0; r < 8; r++)
#pragma unroll
                for (int c = 0; c < 8; c++)
                    acc[r][c] += a[r] * b[c];
        }
        __syncthreads();
    }

#pragma unroll
    for (int r = 0; r < 8; r++) {
        int row = row0 + tr * 8 + r;
        if (row < N_NODES) {
            *(float4*)&Out[row * DIM + tc * 4] =
                make_float4(acc[r][0], acc[r][1], acc[r][2], acc[r][3]);
            *(float4*)&Out[row * DIM + 64 + tc * 4] =
                make_float4(acc[r][4], acc[r][5], acc[r][6], acc[r][7]);
        }
    }
}

// ---------------- CSR gather aggregation ----------------
__global__ void k_gather(const float* __restrict__ tmp, const float* __restrict__ bias,
                         float* __restrict__ out) {
    int node = (int)((blockIdx.x * (unsigned)blockDim.x + threadIdx.x) >> 5);
    int lane = threadIdx.x & 31;
    if (node >= N_NODES) return;

    int beg = g_off[node];
    int end = g_off[node + 1];
    float dd = g_dinv[node];
    float self = dd * dd;

    float4 v = *(const float4*)&tmp[node * DIM + lane * 4];
    float4 acc = make_float4(v.x * self, v.y * self, v.z * self, v.w * self);

    int e = beg;
    for (; e + 3 < end; e += 4) {
        int2 m0 = g_edge[e + 0];
        int2 m1 = g_edge[e + 1];
        int2 m2 = g_edge[e + 2];
        int2 m3 = g_edge[e + 3];
        float4 v0 = *(const float4*)&tmp[m0.x * DIM + lane * 4];
        float4 v1 = *(const float4*)&tmp[m1.x * DIM + lane * 4];
        float4 v2 = *(const float4*)&tmp[m2.x * DIM + lane * 4];
        float4 v3 = *(const float4*)&tmp[m3.x * DIM + lane * 4];
        float n0 = __int_as_float(m0.y), n1 = __int_as_float(m1.y);
        float n2 = __int_as_float(m2.y), n3 = __int_as_float(m3.y);
        acc.x += v0.x * n0 + v1.x * n1 + v2.x * n2 + v3.x * n3;
        acc.y += v0.y * n0 + v1.y * n1 + v2.y * n2 + v3.y * n3;
        acc.z += v0.z * n0 + v1.z * n1 + v2.z * n2 + v3.z * n3;
        acc.w += v0.w * n0 + v1.w * n1 + v2.w * n2 + v3.w * n3;
    }
    for (; e < end; e++) {
        int2 m0 = g_edge[e];
        float n0 = __int_as_float(m0.y);
        float4 v0 = *(const float4*)&tmp[m0.x * DIM + lane * 4];
        acc.x += v0.x * n0; acc.y += v0.y * n0;
        acc.z += v0.z * n0; acc.w += v0.w * n0;
    }

    float4 bb = *(const float4*)&bias[lane * 4];
    acc.x += bb.x; acc.y += bb.y; acc.z += bb.z; acc.w += bb.w;
    *(float4*)&out[node * DIM + lane * 4] = acc;
}

// ---------------- launch ----------------
extern "C" void kernel_launch(void* const* d_in, const int* in_sizes, int n_in,
                              void* d_out, int out_size) {
    const float* x  = (const float*)d_in[0];
    const int*   ei = (const int*)d_in[1];
    const float* W1 = (const float*)d_in[2];
    const float* b1 = (const float*)d_in[3];
    const float* W2 = (const float*)d_in[4];
    const float* b2 = (const float*)d_in[5];
    float* out = (float*)d_out;

    float* tmp_p; cudaGetSymbolAddress((void**)&tmp_p, g_tmp);
    float* h_p;   cudaGetSymbolAddress((void**)&h_p,   g_h);

    int nthr = 256;
    int nb_nodes  = (N_NODES + nthr - 1) / nthr;
    int nb_edges  = (N_EDGES + nthr - 1) / nthr;
    int nb_gemm   = (N_NODES + 127) / 128;
    int nb_gather = (N_NODES * 32 + nthr - 1) / nthr;

    // Side stream: gemm1 (depends only on x, W1) overlaps the CSR build.
    cudaStream_t s2;
    cudaStreamCreateWithFlags(&s2, cudaStreamNonBlocking);
    cudaEvent_t evFork, evJoin;
    cudaEventCreateWithFlags(&evFork, cudaEventDisableTiming);
    cudaEventCreateWithFlags(&evJoin, cudaEventDisableTiming);

    cudaEventRecord(evFork, 0);              // fork from capture (legacy) stream
    cudaStreamWaitEvent(s2, evFork, 0);
    k_gemm<false><<<nb_gemm, nthr, 0, s2>>>(x, W1, tmp_p);
    cudaEventRecord(evJoin, s2);

    // CSR build chain on the main stream (runs concurrently with gemm1)
    k_zero_cnt<<<nb_nodes, nthr>>>();
    k_hist<<<nb_edges, nthr>>>(ei);
    k_scan1<<<SCAN_NB, 256>>>();
    k_scan3<<<SCAN_NB, 256>>>();
    k_scatter<<<nb_edges, nthr>>>(ei);

    cudaStreamWaitEvent(0, evJoin, 0);       // join gemm1 back before gather1

    // layer 1 aggregation
    k_gather<<<nb_gather, nthr>>>(tmp_p, b1, h_p);

    // layer 2
    k_gemm<true><<<nb_gemm, nthr>>>(h_p, W2, tmp_p);
    k_gather<<<nb_gather, nthr>>>(tmp_p, b2, out);
}

// round 8
// speedup vs baseline: 1.2129x; 1.0499x over previous
#include <cuda_runtime.h>
#include <cuda_fp16.h>
#include <cstdint>

#define N_NODES 50000
#define N_EDGES 800000
#define DIM 128
#define SCAN_NB ((N_NODES + 255) / 256)   // 196 blocks

// Scratch (device globals)
__device__ int    g_cnt[N_NODES];
__device__ int    g_off[N_NODES + 1];
__device__ int    g_cur[N_NODES];
__device__ int    g_bsum[SCAN_NB];
__device__ float  g_dinv[N_NODES];
__device__ int2   g_edge[N_EDGES];        // {src, norm bits} CSR-by-dst order
__device__ float  g_tmp[N_NODES * DIM];   // GEMM output fp32
__device__ __half g_tmph[N_NODES * DIM];  // GEMM output fp16 mirror (gather reads)
__device__ float  g_h[N_NODES * DIM];

// ---------------- degree / CSR build ----------------
__global__ void k_zero_cnt() {
    int i = blockIdx.x * blockDim.x + threadIdx.x;
    if (i < N_NODES) g_cnt[i] = 0;
}

__global__ void k_hist(const int* __restrict__ ei) {
    int e = blockIdx.x * blockDim.x + threadIdx.x;
    if (e < N_EDGES) atomicAdd(&g_cnt[ei[N_EDGES + e]], 1);
}

// scan phase 1 + dinv fused
__global__ void k_scan1() {
    __shared__ int s[256];
    int tid = threadIdx.x;
    int i = blockIdx.x * 256 + tid;
    int v = (i < N_NODES) ? g_cnt[i] : 0;
    if (i < N_NODES) g_dinv[i] = rsqrtf((float)(v + 1));   // +1 self-loop
    s[tid] = v;
    __syncthreads();
#pragma unroll
    for (int d = 1; d < 256; d <<= 1) {
        int t = (tid >= d) ? s[tid - d] : 0;
        __syncthreads();
        s[tid] += t;
        __syncthreads();
    }
    if (i < N_NODES) g_off[i] = s[tid] - v;
    if (tid == 255) g_bsum[blockIdx.x] = s[255];
}

// scan phase 2: per-block redundant reduction of global offset
__global__ void k_scan3() {
    __shared__ int red[256];
    int b = blockIdx.x;
    int t = threadIdx.x;
    int partial = 0;
    for (int j = t; j < b; j += 256) partial += g_bsum[j];
    red[t] = partial;
    __syncthreads();
#pragma unroll
    for (int d = 128; d > 0; d >>= 1) {
        if (t < d) red[t] += red[t + d];
        __syncthreads();
    }
    int boff = red[0];
    int i = b * 256 + t;
    if (i < N_NODES) {
        int o = g_off[i] + boff;
        g_off[i] = o;
        g_cur[i] = o;
    }
    if (i == 0) g_off[N_NODES] = N_EDGES;
}

__global__ void k_scatter(const int* __restrict__ ei) {
    int e = blockIdx.x * blockDim.x + threadIdx.x;
    if (e >= N_EDGES) return;
    int src = ei[e];
    int dst = ei[N_EDGES + e];
    int pos = atomicAdd(&g_cur[dst], 1);
    float norm = g_dinv[src] * g_dinv[dst];
    g_edge[pos] = make_int2(src, __float_as_int(norm));
}

// ---------------- FFMA GEMM: Out = act(X) @ W, dual fp32+fp16 epilogue ----------------
template<bool RELU>
__global__ void __launch_bounds__(256, 2)
k_gemm(const float* __restrict__ X, const float* __restrict__ W,
       float* __restrict__ Out, __half* __restrict__ OutH) {
    __shared__ float sW[16][DIM];
    __shared__ float sX[16][132];

    int tid = threadIdx.x;
    int tc = tid & 15, tr = tid >> 4;
    int row0 = blockIdx.x * 128;

    float acc[8][8];
#pragma unroll
    for (int r = 0; r < 8; r++)
#pragma unroll
        for (int c = 0; c < 8; c++) acc[r][c] = 0.f;

    for (int kk = 0; kk < DIM; kk += 16) {
#pragma unroll
        for (int i = 0; i < 2; i++) {
            int lin = (i * 256 + tid) * 4;
            int k = lin >> 7, c = lin & 127;
            *(float4*)&sW[k][c] = *(const float4*)&W[(kk + k) * DIM + c];
        }
#pragma unroll
        for (int i = 0; i < 2; i++) {
            int lin = (i * 256 + tid) * 4;
            int r = lin >> 4, c = lin & 15;
            int row = row0 + r;
            float4 v = make_float4(0.f, 0.f, 0.f, 0.f);
            if (row < N_NODES) v = *(const float4*)&X[row * DIM + kk + c];
            if (RELU) {
                v.x = fmaxf(v.x, 0.f); v.y = fmaxf(v.y, 0.f);
                v.z = fmaxf(v.z, 0.f); v.w = fmaxf(v.w, 0.f);
            }
            sX[c + 0][r] = v.x; sX[c + 1][r] = v.y;
            sX[c + 2][r] = v.z; sX[c + 3][r] = v.w;
        }
        __syncthreads();

#pragma unroll
        for (int k = 0; k < 16; k++) {
            float a[8], b[8];
            *(float4*)&b[0] = *(float4*)&sW[k][tc * 4];
            *(float4*)&b[4] = *(float4*)&sW[k][tc * 4 + 64];
            *(float4*)&a[0] = *(float4*)&sX[k][tr * 8];
            *(float4*)&a[4] = *(float4*)&sX[k][tr * 8 + 4];
#pragma unroll
            for (int r = 0; r < 8; r++)
#pragma unroll
                for (int c = 0; c < 8; c++)
                    acc[r][c] += a[r] * b[c];
        }
        __syncthreads();
    }

#pragma unroll
    for (int r = 0; r < 8; r++) {
        int row = row0 + tr * 8 + r;
        if (row < N_NODES) {
            *(float4*)&Out[row * DIM + tc * 4] =
                make_float4(acc[r][0], acc[r][1], acc[r][2], acc[r][3]);
            *(float4*)&Out[row * DIM + 64 + tc * 4] =
                make_float4(acc[r][4], acc[r][5], acc[r][6], acc[r][7]);
            __half2 h0 = __floats2half2_rn(acc[r][0], acc[r][1]);
            __half2 h1 = __floats2half2_rn(acc[r][2], acc[r][3]);
            __half2 h2 = __floats2half2_rn(acc[r][4], acc[r][5]);
            __half2 h3 = __floats2half2_rn(acc[r][6], acc[r][7]);
            *(__half2*)&OutH[row * DIM + tc * 4 + 0]  = h0;
            *(__half2*)&OutH[row * DIM + tc * 4 + 2]  = h1;
            *(__half2*)&OutH[row * DIM + 64 + tc * 4 + 0] = h2;
            *(__half2*)&OutH[row * DIM + 64 + tc * 4 + 2] = h3;
        }
    }
}

// ---------------- CSR gather aggregation ----------------
// Self term from fp32 tmp; neighbor rows from fp16 mirror (half the L2 bytes).
__device__ __forceinline__ void acc_half(float4& acc, uint2 p, float n) {
    float2 lo = __half22float2(*(__half2*)&p.x);
    float2 hi = __half22float2(*(__half2*)&p.y);
    acc.x += lo.x * n; acc.y += lo.y * n;
    acc.z += hi.x * n; acc.w += hi.y * n;
}

__global__ void k_gather(const float* __restrict__ tmp, const __half* __restrict__ tmph,
                         const float* __restrict__ bias, float* __restrict__ out) {
    int node = (int)((blockIdx.x * (unsigned)blockDim.x + threadIdx.x) >> 5);
    int lane = threadIdx.x & 31;
    if (node >= N_NODES) return;

    int beg = g_off[node];
    int end = g_off[node + 1];
    float dd = g_dinv[node];
    float self = dd * dd;

    float4 v = *(const float4*)&tmp[node * DIM + lane * 4];
    float4 acc = make_float4(v.x * self, v.y * self, v.z * self, v.w * self);

    int e = beg;
    for (; e + 3 < end; e += 4) {
        int2 m0 = g_edge[e + 0];
        int2 m1 = g_edge[e + 1];
        int2 m2 = g_edge[e + 2];
        int2 m3 = g_edge[e + 3];
        uint2 p0 = *(const uint2*)&tmph[m0.x * DIM + lane * 4];
        uint2 p1 = *(const uint2*)&tmph[m1.x * DIM + lane * 4];
        uint2 p2 = *(const uint2*)&tmph[m2.x * DIM + lane * 4];
        uint2 p3 = *(const uint2*)&tmph[m3.x * DIM + lane * 4];
        acc_half(acc, p0, __int_as_float(m0.y));
        acc_half(acc, p1, __int_as_float(m1.y));
        acc_half(acc, p2, __int_as_float(m2.y));
        acc_half(acc, p3, __int_as_float(m3.y));
    }
    for (; e < end; e++) {
        int2 m0 = g_edge[e];
        uint2 p0 = *(const uint2*)&tmph[m0.x * DIM + lane * 4];
        acc_half(acc, p0, __int_as_float(m0.y));
    }

    float4 bb = *(const float4*)&bias[lane * 4];
    acc.x += bb.x; acc.y += bb.y; acc.z += bb.z; acc.w += bb.w;
    *(float4*)&out[node * DIM + lane * 4] = acc;
}

// ---------------- launch ----------------
extern "C" void kernel_launch(void* const* d_in, const int* in_sizes, int n_in,
                              void* d_out, int out_size) {
    const float* x  = (const float*)d_in[0];
    const int*   ei = (const int*)d_in[1];
    const float* W1 = (const float*)d_in[2];
    const float* b1 = (const float*)d_in[3];
    const float* W2 = (const float*)d_in[4];
    const float* b2 = (const float*)d_in[5];
    float* out = (float*)d_out;

    float*  tmp_p;  cudaGetSymbolAddress((void**)&tmp_p,  g_tmp);
    __half* tmph_p; cudaGetSymbolAddress((void**)&tmph_p, g_tmph);
    float*  h_p;    cudaGetSymbolAddress((void**)&h_p,    g_h);

    int nthr = 256;
    int nb_nodes  = (N_NODES + nthr - 1) / nthr;
    int nb_edges  = (N_EDGES + nthr - 1) / nthr;
    int nb_gemm   = (N_NODES + 127) / 128;
    int nb_gather = (N_NODES * 32 + nthr - 1) / nthr;

    // Side stream: gemm1 overlaps the CSR build.
    cudaStream_t s2;
    cudaStreamCreateWithFlags(&s2, cudaStreamNonBlocking);
    cudaEvent_t evFork, evJoin;
    cudaEventCreateWithFlags(&evFork, cudaEventDisableTiming);
    cudaEventCreateWithFlags(&evJoin, cudaEventDisableTiming);

    cudaEventRecord(evFork, 0);
    cudaStreamWaitEvent(s2, evFork, 0);
    k_gemm<false><<<nb_gemm, nthr, 0, s2>>>(x, W1, tmp_p, tmph_p);
    cudaEventRecord(evJoin, s2);

    // CSR build chain (concurrent with gemm1)
    k_zero_cnt<<<nb_nodes, nthr>>>();
    k_hist<<<nb_edges, nthr>>>(ei);
    k_scan1<<<SCAN_NB, 256>>>();
    k_scan3<<<SCAN_NB, 256>>>();
    k_scatter<<<nb_edges, nthr>>>(ei);

    cudaStreamWaitEvent(0, evJoin, 0);

    // layer 1 aggregation
    k_gather<<<nb_gather, nthr>>>(tmp_p, tmph_p, b1, h_p);

    // layer 2
    k_gemm<true><<<nb_gemm, nthr>>>(h_p, W2, tmp_p, tmph_p);
    k_gather<<<nb_gather, nthr>>>(tmp_p, tmph_p, b2, out);
}

// round 10
// speedup vs baseline: 1.6608x; 1.3693x over previous
#include <cuda_runtime.h>
#include <cuda_fp16.h>
#include <cstdint>

#define N_NODES 50000
#define N_EDGES 800000
#define DIM 128
#define SCAN_NB ((N_NODES + 255) / 256)   // 196 blocks

// Scratch (device globals)
__device__ int    g_cnt[N_NODES];
__device__ int    g_off[N_NODES + 1];
__device__ int    g_cur[N_NODES];
__device__ int    g_bsum[SCAN_NB];
__device__ float  g_dinv[N_NODES];
__device__ int2   g_edge[N_EDGES];        // {src, norm bits} CSR-by-dst order
__device__ float  g_tmp[N_NODES * DIM];   // GEMM output fp32
__device__ __half g_tmph[N_NODES * DIM];  // GEMM output fp16 mirror (gather reads)
__device__ float  g_h[N_NODES * DIM];

// ---------------- degree / CSR build ----------------
__global__ void k_zero_cnt() {
    int i = blockIdx.x * blockDim.x + threadIdx.x;
    if (i < N_NODES) g_cnt[i] = 0;
}

__global__ void k_hist(const int* __restrict__ ei) {
    int e = blockIdx.x * blockDim.x + threadIdx.x;
    if (e < N_EDGES) atomicAdd(&g_cnt[ei[N_EDGES + e]], 1);
}

__global__ void k_scan1() {
    __shared__ int s[256];
    int tid = threadIdx.x;
    int i = blockIdx.x * 256 + tid;
    int v = (i < N_NODES) ? g_cnt[i] : 0;
    if (i < N_NODES) g_dinv[i] = rsqrtf((float)(v + 1));   // +1 self-loop
    s[tid] = v;
    __syncthreads();
#pragma unroll
    for (int d = 1; d < 256; d <<= 1) {
        int t = (tid >= d) ? s[tid - d] : 0;
        __syncthreads();
        s[tid] += t;
        __syncthreads();
    }
    if (i < N_NODES) g_off[i] = s[tid] - v;
    if (tid == 255) g_bsum[blockIdx.x] = s[255];
}

__global__ void k_scan3() {
    __shared__ int red[256];
    int b = blockIdx.x;
    int t = threadIdx.x;
    int partial = 0;
    for (int j = t; j < b; j += 256) partial += g_bsum[j];
    red[t] = partial;
    __syncthreads();
#pragma unroll
    for (int d = 128; d > 0; d >>= 1) {
        if (t < d) red[t] += red[t + d];
        __syncthreads();
    }
    int boff = red[0];
    int i = b * 256 + t;
    if (i < N_NODES) {
        int o = g_off[i] + boff;
        g_off[i] = o;
        g_cur[i] = o;
    }
    if (i == 0) g_off[N_NODES] = N_EDGES;
}

__global__ void k_scatter(const int* __restrict__ ei) {
    int e = blockIdx.x * blockDim.x + threadIdx.x;
    if (e >= N_EDGES) return;
    int src = ei[e];
    int dst = ei[N_EDGES + e];
    int pos = atomicAdd(&g_cur[dst], 1);
    float norm = g_dinv[src] * g_dinv[dst];
    g_edge[pos] = make_int2(src, __float_as_int(norm));
}

// ---------------- fp16 HMMA GEMM: Out = act(X) @ W ----------------
__device__ __forceinline__ uint32_t smem_u32(const void* p) {
    return (uint32_t)__cvta_generic_to_shared(p);
}
__device__ __forceinline__ void ldsm_x4(uint32_t addr, uint32_t& r0, uint32_t& r1,
                                        uint32_t& r2, uint32_t& r3) {
    asm volatile("ldmatrix.sync.aligned.m8n8.x4.shared.b16 {%0,%1,%2,%3},[%4];"
        : "=r"(r0), "=r"(r1), "=r"(r2), "=r"(r3) : "r"(addr));
}
__device__ __forceinline__ void ldsm_x4_t(uint32_t addr, uint32_t& r0, uint32_t& r1,
                                          uint32_t& r2, uint32_t& r3) {
    asm volatile("ldmatrix.sync.aligned.m8n8.x4.trans.shared.b16 {%0,%1,%2,%3},[%4];"
        : "=r"(r0), "=r"(r1), "=r"(r2), "=r"(r3) : "r"(addr));
}
__device__ __forceinline__ void mma_f16(float* d, const uint32_t* a, uint32_t b0, uint32_t b1) {
    asm volatile("mma.sync.aligned.m16n8k16.row.col.f32.f16.f16.f32 "
        "{%0,%1,%2,%3},{%4,%5,%6,%7},{%8,%9},{%0,%1,%2,%3};"
        : "+f"(d[0]), "+f"(d[1]), "+f"(d[2]), "+f"(d[3])
        : "r"(a[0]), "r"(a[1]), "r"(a[2]), "r"(a[3]), "r"(b0), "r"(b1));
}

#define XS 72    // sX stride (halves): 144B rows, ldmatrix conflict-free
#define WS 136   // sW stride (halves): 272B rows, ldmatrix conflict-free

template<bool RELU>
__global__ void __launch_bounds__(256, 2)
k_gemm(const float* __restrict__ X, const float* __restrict__ W,
       float* __restrict__ Out, __half* __restrict__ OutH) {
    __shared__ __align__(16) __half sX[128 * XS];   // [m 0..127][k 0..63]
    __shared__ __align__(16) __half sW[64 * WS];    // [k 0..63][n 0..127]

    int tid  = threadIdx.x;
    int warp = tid >> 5;
    int lane = tid & 31;
    int g    = lane >> 2, tg = lane & 3;
    int row0 = blockIdx.x * 128;
    int R0 = (warp & 3) * 32;     // warp row group (32 rows)
    int C0 = (warp >> 2) * 64;    // warp col group (64 cols)

    float acc[2][8][4];
#pragma unroll
    for (int mf = 0; mf < 2; mf++)
#pragma unroll
        for (int nf = 0; nf < 8; nf++)
#pragma unroll
            for (int c = 0; c < 4; c++) acc[mf][nf][c] = 0.f;

    // precomputed ldmatrix lane addresses (constant offsets added per use)
    int lr = lane & 15, lc = lane >> 4;   // row-within-16, 16B col half

    for (int kk = 0; kk < DIM; kk += 64) {
        // fill X chunk: 128 rows x 64 k  (8 float4 per thread)
#pragma unroll
        for (int i = 0; i < 8; i++) {
            int idx = i * 256 + tid;
            int r = idx >> 4, c4 = (idx & 15) * 4;
            int row = row0 + r;
            float4 v = make_float4(0.f, 0.f, 0.f, 0.f);
            if (row < N_NODES) v = *(const float4*)&X[row * DIM + kk + c4];
            if (RELU) {
                v.x = fmaxf(v.x, 0.f); v.y = fmaxf(v.y, 0.f);
                v.z = fmaxf(v.z, 0.f); v.w = fmaxf(v.w, 0.f);
            }
            __half2 h0 = __floats2half2_rn(v.x, v.y);
            __half2 h1 = __floats2half2_rn(v.z, v.w);
            *(__half2*)&sX[r * XS + c4 + 0] = h0;
            *(__half2*)&sX[r * XS + c4 + 2] = h1;
        }
        // fill W chunk: 64 k x 128 n
#pragma unroll
        for (int i = 0; i < 8; i++) {
            int idx = i * 256 + tid;
            int k = idx >> 5, c4 = (idx & 31) * 4;
            float4 v = *(const float4*)&W[(kk + k) * DIM + c4];
            __half2 h0 = __floats2half2_rn(v.x, v.y);
            __half2 h1 = __floats2half2_rn(v.z, v.w);
            *(__half2*)&sW[k * WS + c4 + 0] = h0;
            *(__half2*)&sW[k * WS + c4 + 2] = h1;
        }
        __syncthreads();

#pragma unroll
        for (int ks = 0; ks < 4; ks++) {
            uint32_t a0[4], a1[4];
            ldsm_x4(smem_u32(&sX[(R0 + lr) * XS + ks * 16 + lc * 8]),
                    a0[0], a0[1], a0[2], a0[3]);
            ldsm_x4(smem_u32(&sX[(R0 + 16 + lr) * XS + ks * 16 + lc * 8]),
                    a1[0], a1[1], a1[2], a1[3]);
#pragma unroll
            for (int np = 0; np < 4; np++) {
                uint32_t b0, b1, b2, b3;
                ldsm_x4_t(smem_u32(&sW[(ks * 16 + lr) * WS + C0 + np * 16 + lc * 8]),
                          b0, b1, b2, b3);
                mma_f16(acc[0][2 * np],     a0, b0, b1);
                mma_f16(acc[1][2 * np],     a1, b0, b1);
                mma_f16(acc[0][2 * np + 1], a0, b2, b3);
                mma_f16(acc[1][2 * np + 1], a1, b2, b3);
            }
        }
        __syncthreads();
    }

    // epilogue: fp32 + fp16 mirror
#pragma unroll
    for (int mf = 0; mf < 2; mf++) {
        int r_lo = row0 + R0 + mf * 16 + g;
        int r_hi = r_lo + 8;
#pragma unroll
        for (int nf = 0; nf < 8; nf++) {
            int col = C0 + nf * 8 + 2 * tg;
            float* d = acc[mf][nf];
            if (r_lo < N_NODES) {
                *(float2*)&Out[r_lo * DIM + col] = make_float2(d[0], d[1]);
                *(__half2*)&OutH[r_lo * DIM + col] = __floats2half2_rn(d[0], d[1]);
            }
            if (r_hi < N_NODES) {
                *(float2*)&Out[r_hi * DIM + col] = make_float2(d[2], d[3]);
                *(__half2*)&OutH[r_hi * DIM + col] = __floats2half2_rn(d[2], d[3]);
            }
        }
    }
}

// ---------------- CSR gather aggregation ----------------
__device__ __forceinline__ void acc_half(float4& acc, uint2 p, float n) {
    float2 lo = __half22float2(*(__half2*)&p.x);
    float2 hi = __half22float2(*(__half2*)&p.y);
    acc.x += lo.x * n; acc.y += lo.y * n;
    acc.z += hi.x * n; acc.w += hi.y * n;
}

__global__ void k_gather(const float* __restrict__ tmp, const __half* __restrict__ tmph,
                         const float* __restrict__ bias, float* __restrict__ out) {
    int node = (int)((blockIdx.x * (unsigned)blockDim.x + threadIdx.x) >> 5);
    int lane = threadIdx.x & 31;
    if (node >= N_NODES) return;

    int beg = g_off[node];
    int end = g_off[node + 1];
    float dd = g_dinv[node];
    float self = dd * dd;

    float4 v = *(const float4*)&tmp[node * DIM + lane * 4];
    float4 acc = make_float4(v.x * self, v.y * self, v.z * self, v.w * self);

    int e = beg;
    for (; e + 3 < end; e += 4) {
        int2 m0 = g_edge[e + 0];
        int2 m1 = g_edge[e + 1];
        int2 m2 = g_edge[e + 2];
        int2 m3 = g_edge[e + 3];
        uint2 p0 = *(const uint2*)&tmph[m0.x * DIM + lane * 4];
        uint2 p1 = *(const uint2*)&tmph[m1.x * DIM + lane * 4];
        uint2 p2 = *(const uint2*)&tmph[m2.x * DIM + lane * 4];
        uint2 p3 = *(const uint2*)&tmph[m3.x * DIM + lane * 4];
        acc_half(acc, p0, __int_as_float(m0.y));
        acc_half(acc, p1, __int_as_float(m1.y));
        acc_half(acc, p2, __int_as_float(m2.y));
        acc_half(acc, p3, __int_as_float(m3.y));
    }
    for (; e < end; e++) {
        int2 m0 = g_edge[e];
        uint2 p0 = *(const uint2*)&tmph[m0.x * DIM + lane * 4];
        acc_half(acc, p0, __int_as_float(m0.y));
    }

    float4 bb = *(const float4*)&bias[lane * 4];
    acc.x += bb.x; acc.y += bb.y; acc.z += bb.z; acc.w += bb.w;
    *(float4*)&out[node * DIM + lane * 4] = acc;
}

// ---------------- launch ----------------
extern "C" void kernel_launch(void* const* d_in, const int* in_sizes, int n_in,
                              void* d_out, int out_size) {
    const float* x  = (const float*)d_in[0];
    const int*   ei = (const int*)d_in[1];
    const float* W1 = (const float*)d_in[2];
    const float* b1 = (const float*)d_in[3];
    const float* W2 = (const float*)d_in[4];
    const float* b2 = (const float*)d_in[5];
    float* out = (float*)d_out;

    float*  tmp_p;  cudaGetSymbolAddress((void**)&tmp_p,  g_tmp);
    __half* tmph_p; cudaGetSymbolAddress((void**)&tmph_p, g_tmph);
    float*  h_p;    cudaGetSymbolAddress((void**)&h_p,    g_h);

    int nthr = 256;
    int nb_nodes  = (N_NODES + nthr - 1) / nthr;
    int nb_edges  = (N_EDGES + nthr - 1) / nthr;
    int nb_gemm   = (N_NODES + 127) / 128;
    int nb_gather = (N_NODES * 32 + nthr - 1) / nthr;

    // Side stream: gemm1 overlaps the CSR build.
    cudaStream_t s2;
    cudaStreamCreateWithFlags(&s2, cudaStreamNonBlocking);
    cudaEvent_t evFork, evJoin;
    cudaEventCreateWithFlags(&evFork, cudaEventDisableTiming);
    cudaEventCreateWithFlags(&evJoin, cudaEventDisableTiming);

    cudaEventRecord(evFork, 0);
    cudaStreamWaitEvent(s2, evFork, 0);
    k_gemm<false><<<nb_gemm, nthr, 0, s2>>>(x, W1, tmp_p, tmph_p);
    cudaEventRecord(evJoin, s2);

    // CSR build chain (concurrent with gemm1)
    k_zero_cnt<<<nb_nodes, nthr>>>();
    k_hist<<<nb_edges, nthr>>>(ei);
    k_scan1<<<SCAN_NB, 256>>>();
    k_scan3<<<SCAN_NB, 256>>>();
    k_scatter<<<nb_edges, nthr>>>(ei);

    cudaStreamWaitEvent(0, evJoin, 0);

    // layer 1 aggregation
    k_gather<<<nb_gather, nthr>>>(tmp_p, tmph_p, b1, h_p);

    // layer 2
    k_gemm<true><<<nb_gemm, nthr>>>(h_p, W2, tmp_p, tmph_p);
    k_gather<<<nb_gather, nthr>>>(tmp_p, tmph_p, b2, out);
}